// round 17
// baseline (speedup 1.0000x reference)
#include <cuda_runtime.h>
#include <math.h>

// ---------------------------------------------------------------------------
// Problem constants (fixed by setup_inputs):
//   B=128, T=512, n_in=2, n_rec = n_out = n_init = 512
// ---------------------------------------------------------------------------
#define BN   128
#define TT   512
#define NR   512
#define NIN  2
#define CL   16     // CTAs per cluster (nonportable size, runtime-launched)
#define BG   16     // batch rows per cluster (128 rows / 8 clusters)
#define COLS 32     // n_rec columns per CTA (512 / 16)
#define NTH  512    // threads per CTA (16 warps)
#define NKC  4      // K chunks (128 k each)
#define SHP  (NR + 4)   // padded sH row pitch (4-bank offset between rows)
#define DTAU 0.2f

// Dynamic smem layout (floats):
//   sUz   [NR][COLS]          16384   (persistent Uz slice)
//   sUh   [NR][COLS]          16384   (persistent Uh slice)
//   sH    [BG][SHP]            8256
//   sRed  [2][NKC][BG][COLS]   4096
//   sWin  [3][COLS][NIN]        192
//   sX    [BG][NIN]              32
#define SM_FLOATS (2*NR*COLS + BG*SHP + 2*NKC*BG*COLS + 3*COLS*NIN + BG*NIN)
#define SM_BYTES  (SM_FLOATS * 4)

// Static device scratch (no allocation allowed).
__device__ float g_h[BN * NR];     // h exchange buffer (full state)
__device__ float g_v[BN * NR];     // v = r*h exchange buffer
__device__ float g_UzT[NR * NR];   // W_uz transposed: [k][j]
__device__ float g_UrT[NR * NR];
__device__ float g_UhT[NR * NR];
__device__ float g_WeT[NR * NR];   // W_enc transposed
__device__ float g_WdT[NR * NR];   // W_dec transposed

__device__ __forceinline__ void cluster_sync_all() {
    asm volatile("barrier.cluster.arrive.aligned;" ::: "memory");
    asm volatile("barrier.cluster.wait.aligned;" ::: "memory");
}

__device__ __forceinline__ float sigmoidf_(float x) {
    return 1.0f / (1.0f + expf(-x));
}

// ---------------------------------------------------------------------------
// Transpose all 5 weight matrices (512x512): dst[k][j] = src[j][k]
// grid (16,16,5), block (32,8)
// ---------------------------------------------------------------------------
__global__ void transpose_all(const float* __restrict__ W_uz,
                              const float* __restrict__ W_ur,
                              const float* __restrict__ W_uh,
                              const float* __restrict__ W_enc,
                              const float* __restrict__ W_dec) {
    __shared__ float tile[32][33];
    const float* src;
    float* dst;
    switch (blockIdx.z) {
        case 0: src = W_uz;  dst = g_UzT; break;
        case 1: src = W_ur;  dst = g_UrT; break;
        case 2: src = W_uh;  dst = g_UhT; break;
        case 3: src = W_enc; dst = g_WeT; break;
        default: src = W_dec; dst = g_WdT; break;
    }
    const int bx = blockIdx.x * 32, by = blockIdx.y * 32;
    const int tx = threadIdx.x, ty = threadIdx.y;
#pragma unroll
    for (int i = 0; i < 32; i += 8)
        tile[ty + i][tx] = src[(size_t)(by + ty + i) * NR + bx + tx];
    __syncthreads();
#pragma unroll
    for (int i = 0; i < 32; i += 8)
        dst[(size_t)(bx + ty + i) * NR + by + tx] = tile[tx][ty + i];
}

// ---------------------------------------------------------------------------
// Encoder: g_h[b][j] = sum_k init[b][k] * WeT[k][j]
// grid (128, 4), 128 threads
// ---------------------------------------------------------------------------
__global__ void encoder_kernel(const float* __restrict__ init_state) {
    __shared__ float sI[NR];
    const int b = blockIdx.x;
    const int j = blockIdx.y * 128 + threadIdx.x;
    for (int i = threadIdx.x; i < NR; i += 128)
        sI[i] = init_state[(size_t)b * NR + i];
    __syncthreads();
    float acc = 0.0f;
#pragma unroll 8
    for (int k = 0; k < NR; k++)
        acc = fmaf(sI[k], g_WeT[(size_t)k * NR + j], acc);
    g_h[(size_t)b * NR + j] = acc;
}

// ---------------------------------------------------------------------------
// Persistent recurrent kernel.
// Grid = 128 CTAs = 8 independent clusters of 16 (runtime cluster dims).
// Cluster owns 16 batch rows; CTA owns 32 recurrent columns.
// Uz and Uh slices (64KB each) are SMEM-resident; Ur streams from L2.
// Thread tile: 1 row x 4 cols, K split into 4 chunks of 128.
// ---------------------------------------------------------------------------
__global__ void __launch_bounds__(NTH, 1)
rnn_persistent(const float* __restrict__ x,
               const float* __restrict__ W_wz,
               const float* __restrict__ W_wr,
               const float* __restrict__ W_wh,
               float* __restrict__ out_h)
{
    extern __shared__ float dynsm[];
    float (*sUz)[COLS]            = (float (*)[COLS])dynsm;
    float* p = dynsm + NR * COLS;
    float (*sUh)[COLS]            = (float (*)[COLS])p;           p += NR * COLS;
    float (*sH)[SHP]              = (float (*)[SHP])p;            p += BG * SHP;
    float (*sRed)[NKC][BG][COLS]  = (float (*)[NKC][BG][COLS])p;  p += 2 * NKC * BG * COLS;
    float (*sWin)[COLS][NIN]      = (float (*)[COLS][NIN])p;      p += 3 * COLS * NIN;
    float (*sX)[NIN]              = (float (*)[NIN])p;

    const int tid     = threadIdx.x;
    const int cta     = blockIdx.x;
    const int cl      = cta / CL;
    const int rank    = cta % CL;
    const int b0      = cl * BG;
    const int colbase = rank * COLS;

    // GEMM thread mapping: tid = kc*128 + b*8 + jg.
    const int kc = tid >> 7;              // 0..3   (K chunk of 128)
    const int bb = (tid >> 3) & 15;       // 0..15  (batch row)
    const int jg = tid & 7;               // 0..7
    const int j0 = jg << 2;               // 0,4,...,28
    const int kb = kc << 7;               // K chunk base

    // Epilogue mapping: one output element per thread (512 = 16*32).
    const int eb = tid >> 5;              // batch row 0..15
    const int ej = tid & 31;              // column 0..31

    // Load input-projection weight slices (n_in = 2).
    if (tid < COLS) {
        const int j = colbase + tid;
        sWin[0][tid][0] = W_wz[j * NIN + 0];
        sWin[0][tid][1] = W_wz[j * NIN + 1];
        sWin[1][tid][0] = W_wr[j * NIN + 0];
        sWin[1][tid][1] = W_wr[j * NIN + 1];
        sWin[2][tid][0] = W_wh[j * NIN + 0];
        sWin[2][tid][1] = W_wh[j * NIN + 1];
    }

    // Preload Uz and Uh column slices into SMEM (persistent for all steps).
    // Each: 512 rows x 32 cols = 4096 float4, 8 per thread.
    for (int i = tid; i < NR * (COLS / 4); i += NTH) {
        const int k = i >> 3, jf = i & 7;
        reinterpret_cast<float4*>(&sUz[k][0])[jf] =
            __ldcg(reinterpret_cast<const float4*>(g_UzT + (size_t)k * NR + colbase) + jf);
        reinterpret_cast<float4*>(&sUh[k][0])[jf] =
            __ldcg(reinterpret_cast<const float4*>(g_UhT + (size_t)k * NR + colbase) + jf);
    }

    // Load h0 (written by encoder_kernel) into sH.
    for (int i = tid; i < BG * (NR / 4); i += NTH) {
        const int b = i >> 7, idx = i & 127;
        reinterpret_cast<float4*>(&sH[b][0])[idx] =
            __ldcv(reinterpret_cast<const float4*>(g_h + (size_t)(b0 + b) * NR) + idx);
    }
    __syncthreads();

    const float* __restrict__ urBase = g_UrT + (size_t)kb * NR + colbase + j0;

    for (int t = 0; t < TT; t++) {
        // Load x_t for our 16 rows.
        if (tid < BG * NIN) {
            const int b = tid >> 1, c = tid & 1;
            sX[b][c] = x[((size_t)(b0 + b) * TT + t) * NIN + c];
        }

        float z_save, h_save;   // carried from epilogue 1 to epilogue 2

        // ---------------- Phase 1: z (SMEM weights), r (L2 weights) ---------
        {
            float az0 = 0, az1 = 0, az2 = 0, az3 = 0;
            float ar0 = 0, ar1 = 0, ar2 = 0, ar3 = 0;
            const float* __restrict__ hrow = &sH[bb][kb];
#pragma unroll 4
            for (int g = 0; g < 32; g++) {
                const float4 hv = *reinterpret_cast<const float4*>(hrow + (g << 2));
#pragma unroll
                for (int i = 0; i < 4; i++) {
                    const int k = (g << 2) + i;
                    const float4 wz = *reinterpret_cast<const float4*>(&sUz[kb + k][j0]);
                    const float4 wr = __ldcg(reinterpret_cast<const float4*>(
                        urBase + (size_t)k * NR));
                    const float hval = (&hv.x)[i];
                    az0 = fmaf(hval, wz.x, az0); az1 = fmaf(hval, wz.y, az1);
                    az2 = fmaf(hval, wz.z, az2); az3 = fmaf(hval, wz.w, az3);
                    ar0 = fmaf(hval, wr.x, ar0); ar1 = fmaf(hval, wr.y, ar1);
                    ar2 = fmaf(hval, wr.z, ar2); ar3 = fmaf(hval, wr.w, ar3);
                }
            }
            *reinterpret_cast<float4*>(&sRed[0][kc][bb][j0]) = make_float4(az0, az1, az2, az3);
            *reinterpret_cast<float4*>(&sRed[1][kc][bb][j0]) = make_float4(ar0, ar1, ar2, ar3);
        }
        __syncthreads();

        // Phase 1 epilogue: reduce chunks, gates, v = r*h (own slice -> g_v).
        {
            float sz = 0.0f, sr = 0.0f;
#pragma unroll
            for (int c = 0; c < NKC; c++) {
                sz += sRed[0][c][eb][ej];
                sr += sRed[1][c][eb][ej];
            }
            const float xz = sX[eb][0] * sWin[0][ej][0] + sX[eb][1] * sWin[0][ej][1];
            const float xr = sX[eb][0] * sWin[1][ej][0] + sX[eb][1] * sWin[1][ej][1];
            const float z  = sigmoidf_(xz + sz);
            const float r  = sigmoidf_(xr + sr);
            const float hc = sH[eb][colbase + ej];
            z_save = z;
            h_save = hc;
            g_v[(size_t)(b0 + eb) * NR + colbase + ej] = r * hc;
        }
        cluster_sync_all();   // all v slices visible cluster-wide

        // Refill sH with full v.
        for (int i = tid; i < BG * (NR / 4); i += NTH) {
            const int b = i >> 7, idx = i & 127;
            reinterpret_cast<float4*>(&sH[b][0])[idx] =
                __ldcv(reinterpret_cast<const float4*>(g_v + (size_t)(b0 + b) * NR) + idx);
        }
        __syncthreads();

        // ---------------- Phase 2: candidate GEMM (SMEM weights) ------------
        {
            float au0 = 0, au1 = 0, au2 = 0, au3 = 0;
            const float* __restrict__ vrow = &sH[bb][kb];
#pragma unroll 4
            for (int g = 0; g < 32; g++) {
                const float4 vv = *reinterpret_cast<const float4*>(vrow + (g << 2));
#pragma unroll
                for (int i = 0; i < 4; i++) {
                    const int k = (g << 2) + i;
                    const float4 wh = *reinterpret_cast<const float4*>(&sUh[kb + k][j0]);
                    const float vval = (&vv.x)[i];
                    au0 = fmaf(vval, wh.x, au0); au1 = fmaf(vval, wh.y, au1);
                    au2 = fmaf(vval, wh.z, au2); au3 = fmaf(vval, wh.w, au3);
                }
            }
            *reinterpret_cast<float4*>(&sRed[0][kc][bb][j0]) = make_float4(au0, au1, au2, au3);
        }
        __syncthreads();

        // Phase 2 epilogue: u, tanh, leaky update; write h_t to output + g_h.
        {
            float su = 0.0f;
#pragma unroll
            for (int c = 0; c < NKC; c++)
                su += sRed[0][c][eb][ej];
            const float xh = sX[eb][0] * sWin[2][ej][0] + sX[eb][1] * sWin[2][ej][1];
            const float u  = xh + su;
            const float hn = h_save + DTAU * (z_save - 1.0f) * (h_save - tanhf(u));
            out_h[((size_t)(b0 + eb) * TT + t) * NR + colbase + ej] = hn;
            g_h[(size_t)(b0 + eb) * NR + colbase + ej] = hn;
        }
        cluster_sync_all();   // all new-h slices visible cluster-wide

        // Refill sH with full new h for next step.
        for (int i = tid; i < BG * (NR / 4); i += NTH) {
            const int b = i >> 7, idx = i & 127;
            reinterpret_cast<float4*>(&sH[b][0])[idx] =
                __ldcv(reinterpret_cast<const float4*>(g_h + (size_t)(b0 + b) * NR) + idx);
        }
        __syncthreads();
    }
}

// ---------------------------------------------------------------------------
// Decoder GEMM: y[bt][o] = sum_r h[bt][r] * W_dec[o][r]
//             = A (65536 x 512) * g_WdT (512 x 512)
// 128x128 block tile, K-tile 8, 8x8 thread tile (2x2 quadrants of 4).
// grid (4, 512), 256 threads.
// ---------------------------------------------------------------------------
__global__ void __launch_bounds__(256)
decoder_gemm(const float* __restrict__ A, float* __restrict__ C) {
    __shared__ float As[8][128];
    __shared__ float Bs[8][128];

    const int tid = threadIdx.x;
    const int tx = tid & 15;       // 16
    const int ty = tid >> 4;       // 16
    const int m0 = blockIdx.y * 128;
    const int n0 = blockIdx.x * 128;

    float acc[8][8];
#pragma unroll
    for (int i = 0; i < 8; i++)
#pragma unroll
        for (int j = 0; j < 8; j++) acc[i][j] = 0.0f;

    const int lrow = tid >> 1;          // 0..127
    const int lk   = (tid & 1) << 2;    // 0 or 4
    const int brow = tid >> 5;          // 0..7
    const int bcol = (tid & 31) << 2;   // 0..124

    for (int k0 = 0; k0 < NR; k0 += 8) {
        const float4 av = *reinterpret_cast<const float4*>(
            A + (size_t)(m0 + lrow) * NR + k0 + lk);
        As[lk + 0][lrow] = av.x;
        As[lk + 1][lrow] = av.y;
        As[lk + 2][lrow] = av.z;
        As[lk + 3][lrow] = av.w;
        *reinterpret_cast<float4*>(&Bs[brow][bcol]) =
            *reinterpret_cast<const float4*>(
                g_WdT + (size_t)(k0 + brow) * NR + n0 + bcol);
        __syncthreads();

#pragma unroll
        for (int kk = 0; kk < 8; kk++) {
            float a[8], b[8];
            *reinterpret_cast<float4*>(a)     = *reinterpret_cast<const float4*>(&As[kk][ty * 4]);
            *reinterpret_cast<float4*>(a + 4) = *reinterpret_cast<const float4*>(&As[kk][64 + ty * 4]);
            *reinterpret_cast<float4*>(b)     = *reinterpret_cast<const float4*>(&Bs[kk][tx * 4]);
            *reinterpret_cast<float4*>(b + 4) = *reinterpret_cast<const float4*>(&Bs[kk][64 + tx * 4]);
#pragma unroll
            for (int i = 0; i < 8; i++)
#pragma unroll
                for (int j = 0; j < 8; j++)
                    acc[i][j] = fmaf(a[i], b[j], acc[i][j]);
        }
        __syncthreads();
    }

#pragma unroll
    for (int ri = 0; ri < 2; ri++) {
#pragma unroll
        for (int i = 0; i < 4; i++) {
            const int row = m0 + ri * 64 + ty * 4 + i;
            const int ii = ri * 4 + i;
            *reinterpret_cast<float4*>(C + (size_t)row * NR + n0 + tx * 4) =
                make_float4(acc[ii][0], acc[ii][1], acc[ii][2], acc[ii][3]);
            *reinterpret_cast<float4*>(C + (size_t)row * NR + n0 + 64 + tx * 4) =
                make_float4(acc[ii][4], acc[ii][5], acc[ii][6], acc[ii][7]);
        }
    }
}

// ---------------------------------------------------------------------------
// Launch. Inputs (metadata order): x, init_state, W_enc, W_wz, W_uz, W_wr,
// W_ur, W_wh, W_uh, W_dec. Output: [h_1t | y_1t] concatenated,
// each (B, T, NR) fp32.
// ---------------------------------------------------------------------------
extern "C" void kernel_launch(void* const* d_in, const int* in_sizes, int n_in,
                              void* d_out, int out_size) {
    const float* x     = (const float*)d_in[0];
    const float* init  = (const float*)d_in[1];
    const float* W_enc = (const float*)d_in[2];
    const float* W_wz  = (const float*)d_in[3];
    const float* W_uz  = (const float*)d_in[4];
    const float* W_wr  = (const float*)d_in[5];
    const float* W_ur  = (const float*)d_in[6];
    const float* W_wh  = (const float*)d_in[7];
    const float* W_uh  = (const float*)d_in[8];
    const float* W_dec = (const float*)d_in[9];

    float* out_h = (float*)d_out;
    float* out_y = out_h + (size_t)BN * TT * NR;

    cudaFuncSetAttribute(rnn_persistent,
                         cudaFuncAttributeMaxDynamicSharedMemorySize, SM_BYTES);
    cudaFuncSetAttribute(rnn_persistent,
                         cudaFuncAttributeNonPortableClusterSizeAllowed, 1);

    transpose_all<<<dim3(16, 16, 5), dim3(32, 8)>>>(W_uz, W_ur, W_uh, W_enc, W_dec);
    encoder_kernel<<<dim3(BN, 4), 128>>>(init);

    {
        cudaLaunchConfig_t cfg = {};
        cfg.gridDim = dim3(BN, 1, 1);
        cfg.blockDim = dim3(NTH, 1, 1);
        cfg.dynamicSmemBytes = SM_BYTES;
        cfg.stream = 0;
        cudaLaunchAttribute attrs[1];
        attrs[0].id = cudaLaunchAttributeClusterDimension;
        attrs[0].val.clusterDim.x = CL;
        attrs[0].val.clusterDim.y = 1;
        attrs[0].val.clusterDim.z = 1;
        cfg.attrs = attrs;
        cfg.numAttrs = 1;
        cudaLaunchKernelEx(&cfg, rnn_persistent, x, W_wz, W_wr, W_wh, out_h);
    }

    decoder_gemm<<<dim3(4, 512), 256>>>(out_h, out_y);
}